// round 17
// baseline (speedup 1.0000x reference)
#include <cuda_runtime.h>

// B=4096, NSPIN=2, NPS=16, D=256, NION=8, DIM=3.  8192 (b,s) pairs.
// k1: 456 persistent blocks; depth-2 cp.async pipeline; bank-padded W;
//     envelope sqrt via rsqrt (no IEEE software sqrt).
// k2: warp-sync LU, 2 pairs/warp (single-pair state), redux argmax.

#define NBLK 456

__device__ float g_M[8192 * 256];   // M^T per pair: row o holds M[.][o]

struct __align__(16) Smem1 {
    float xs[2][16 * 260];   // [buf][n][col], col = d ^ 8*((n>>2)&3) ^ 4*((d>>4)&1)
    float W[16 * 272];       // [kgb][dlow][o], stride 272 (bank shift 16)
    float part[8 * 320];     // [slice][tl*20 + r*4 + c]
    float rs2[16 * 8 * 8];   // [n][i][c]
    float rsraw[2][384];
    float4 G4[128];
    float2 G2[128];
    float ei[128];
};

__device__ __forceinline__ void cp_async16(void* smem_dst, const void* gsrc) {
    unsigned sa = (unsigned)__cvta_generic_to_shared(smem_dst);
    asm volatile("cp.async.cg.shared.global [%0], [%1], 16;" :: "r"(sa), "l"(gsrc));
}

__device__ __forceinline__ void prefetch_pair(Smem1& S, int buf,
                                              const float* __restrict__ eq,
                                              const float* __restrict__ rei,
                                              size_t p, int t) {
    const float* xsrc = eq + p * 4096;
    #pragma unroll
    for (int c = 0; c < 4; ++c) {
        int idx = c * 1024 + t * 4;
        int n = idx >> 8, dq = idx & 255;
        int col = dq ^ (((n >> 2) & 3) << 3) ^ (((dq >> 4) & 1) << 2);
        cp_async16(&S.xs[buf][n * 260 + col], xsrc + idx);
    }
    if (t < 96)
        cp_async16(&S.rsraw[buf][t * 4], rei + p * 384 + t * 4);
    asm volatile("cp.async.commit_group;");
}

__global__ void __launch_bounds__(256, 3)
k1_buildM(const float* __restrict__ eq,  const float* __restrict__ rei,
          const float* __restrict__ Wg,  const float* __restrict__ bg,
          const float* __restrict__ edg, const float* __restrict__ eig)
{
    extern __shared__ __align__(16) char smem_raw[];
    Smem1& S = *reinterpret_cast<Smem1*>(smem_raw);
    const int b = blockIdx.x, s = b & 1, t = threadIdx.x;
    const int cnt = (8192 - b + NBLK - 1) / NBLK;

    prefetch_pair(S, 0, eq, rei, (size_t)b, t);
    if (cnt > 1) prefetch_pair(S, 1, eq, rei, (size_t)b + NBLK, t);
    {
        const float* wsrc = Wg + s * 4096;
        #pragma unroll
        for (int c = 0; c < 4; ++c) {
            int idx = c * 1024 + t * 4;
            int d = idx >> 4, o = idx & 15;
            *reinterpret_cast<float4*>(&S.W[(d >> 4) * 272 + (d & 15) * 16 + o]) =
                *reinterpret_cast<const float4*>(wsrc + idx);
        }
        if (t < 128) {
            const float* E = edg + s * 1152 + t * 9;
            float e0=E[0],e1=E[1],e2=E[2],e3=E[3],e4=E[4],e5=E[5],e6=E[6],e7=E[7],e8=E[8];
            S.G4[t] = make_float4(e0*e0 + e3*e3 + e6*e6,
                                  e1*e1 + e4*e4 + e7*e7,
                                  e2*e2 + e5*e5 + e8*e8,
                                  2.f*(e0*e1 + e3*e4 + e6*e7));
            S.G2[t] = make_float2(2.f*(e0*e2 + e3*e5 + e6*e8),
                                  2.f*(e1*e2 + e4*e5 + e7*e8));
            S.ei[t] = eig[s * 128 + t];
        }
    }

    const int kg = t >> 4, tl = t & 15;
    const int a  = tl >> 2;
    const int tn = a << 2, to = (tl & 3) << 2;
    const int wbase = kg * 272 + to;
    const float bias = __ldg(bg + s * 16 + (t & 15));

    for (int j = 0; j < cnt; ++j) {
        const int buf = j & 1;
        const size_t p = (size_t)b + (size_t)j * NBLK;

        asm volatile("cp.async.wait_group 1;");
        __syncthreads();

        if (t < 128) {
            const float* rr = &S.rsraw[buf][t * 3];
            float r0 = rr[0], r1 = rr[1], r2 = rr[2];
            *reinterpret_cast<float4*>(&S.rs2[t * 8]) =
                make_float4(r0 * r0, r1 * r1, r2 * r2, r0 * r1);
            *reinterpret_cast<float4*>(&S.rs2[t * 8 + 4]) =
                make_float4(r0 * r2, r1 * r2, 0.f, 0.f);
        }

        // ---- GEMM: 16 kg x 16 tiles (4n x 4o); xs swizzled, W padded ----
        {
            const int d0 = kg << 4, kb = kg & 1;
            float acc[4][4];
            #pragma unroll
            for (int r = 0; r < 4; ++r)
                #pragma unroll
                for (int c = 0; c < 4; ++c) acc[r][c] = 0.f;

            #pragma unroll
            for (int jj = 0; jj < 16; jj += 4) {
                const int xc = (d0 + jj) ^ (a << 3) ^ (kb << 2);
                float4 xv[4];
                #pragma unroll
                for (int r = 0; r < 4; ++r)
                    xv[r] = *reinterpret_cast<const float4*>(&S.xs[buf][(tn + r) * 260 + xc]);
                #pragma unroll
                for (int u = 0; u < 4; ++u) {
                    float4 wv = *reinterpret_cast<const float4*>(&S.W[wbase + (jj + u) * 16]);
                    #pragma unroll
                    for (int r = 0; r < 4; ++r) {
                        float x = (&xv[r].x)[u];
                        acc[r][0] = fmaf(x, wv.x, acc[r][0]);
                        acc[r][1] = fmaf(x, wv.y, acc[r][1]);
                        acc[r][2] = fmaf(x, wv.z, acc[r][2]);
                        acc[r][3] = fmaf(x, wv.w, acc[r][3]);
                    }
                }
            }
            float* pp = &S.part[(kg & 7) * 320 + tl * 20];
            if (kg < 8) {
                #pragma unroll
                for (int r = 0; r < 4; ++r)
                    *reinterpret_cast<float4*>(pp + r * 4) =
                        make_float4(acc[r][0], acc[r][1], acc[r][2], acc[r][3]);
            }
            __syncthreads();
            if (kg >= 8) {
                #pragma unroll
                for (int r = 0; r < 4; ++r) {
                    float4 v = *reinterpret_cast<float4*>(pp + r * 4);
                    v.x += acc[r][0]; v.y += acc[r][1]; v.z += acc[r][2]; v.w += acc[r][3];
                    *reinterpret_cast<float4*>(pp + r * 4) = v;
                }
            }
            __syncthreads();
        }

        if (j + 2 < cnt)
            prefetch_pair(S, buf, eq, rei, p + 2 * NBLK, t);

        // ---- reduce + envelope; store M^T ----
        {
            const int n = t >> 4, o = t & 15;
            const int base = ((n >> 2) * 4 + (o >> 2)) * 20 + (n & 3) * 4 + (o & 3);
            float y = bias;
            #pragma unroll
            for (int k = 0; k < 8; ++k) y += S.part[k * 320 + base];

            float env = 0.f;
            #pragma unroll
            for (int i = 0; i < 8; ++i) {
                float4 Ga = S.G4[i * 16 + o];
                float2 Gb = S.G2[i * 16 + o];
                float4 Ra = *reinterpret_cast<const float4*>(&S.rs2[(n * 8 + i) * 8]);
                float2 Rb = *reinterpret_cast<const float2*>(&S.rs2[(n * 8 + i) * 8 + 4]);
                float qv = Ga.x * Ra.x;
                qv = fmaf(Ga.y, Ra.y, qv);
                qv = fmaf(Ga.z, Ra.z, qv);
                qv = fmaf(Ga.w, Ra.w, qv);
                qv = fmaf(Gb.x, Rb.x, qv);
                qv = fmaf(Gb.y, Rb.y, qv);
                qv = fmaxf(qv, 1e-30f);
                float sq = qv * __frsqrt_rn(qv);     // sqrt via MUFU.RSQ, no sw sqrt
                env = fmaf(__expf(-sq), S.ei[i * 16 + o], env);
            }
            g_M[p * 256 + o * 16 + n] = y * env;
        }
    }
}

// ---- k2: warp-sync LU + solve; 2 pairs/warp, redux argmax (R14 version) ----
__global__ void __launch_bounds__(256)
k2_solve(float* __restrict__ out)
{
    const int t = threadIdx.x;
    const int w = t >> 5, g = (t >> 4) & 1, lane = t & 31, r = t & 15;
    const int p = blockIdx.x * 16 + w * 2 + g;
    const float* Mp = &g_M[(size_t)p * 256];

    float A[16];
    #pragma unroll
    for (int j = 0; j < 16; j += 4) {
        float4 v = *reinterpret_cast<const float4*>(Mp + r * 16 + j);
        A[j] = v.x; A[j+1] = v.y; A[j+2] = v.z; A[j+3] = v.w;
    }
    float m0  = Mp[r];
    float rhs = (r == 0) ? 1.f : 0.f;
    int mystep = -1;
    float det = 1.f;
    unsigned remaining = 0xFFFFu, parity = 0;
    const unsigned gmask = 0xFFFFu << ((lane >> 4) << 4);

    #pragma unroll
    for (int k = 0; k < 16; ++k) {
        unsigned key = (mystep < 0)
            ? ((__float_as_uint(fabsf(A[k])) & ~31u) | (unsigned)lane)
            : (unsigned)lane;
        unsigned mx = __reduce_max_sync(gmask, key);
        const int pl_lane = (int)(mx & 31u);
        const int plg = pl_lane & 15;
        const float pkk = __shfl_sync(0xFFFFFFFFu, A[k], plg, 16);
        det *= pkk;
        parity += __popc(remaining & ((1u << plg) - 1u));
        remaining &= ~(1u << plg);
        const bool active = (mystep < 0) && (lane != pl_lane);
        if (lane == pl_lane) mystep = k;
        const float f = __fdividef(A[k], pkk);
        #pragma unroll
        for (int j = k + 1; j < 16; ++j) {
            float pv = __shfl_sync(0xFFFFFFFFu, A[j], plg, 16);
            if (active) A[j] = fmaf(-f, pv, A[j]);
        }
        float pr = __shfl_sync(0xFFFFFFFFu, rhs, plg, 16);
        if (active) rhs = fmaf(-f, pr, rhs);
    }

    const float sdet = (parity & 1u) ? -det : det;
    float xk = 0.f;
    #pragma unroll
    for (int c = 15; c >= 0; --c) {
        unsigned bb = __ballot_sync(0xFFFFFFFFu, mystep == c);
        int src = __ffs((bb >> (g * 16)) & 0xFFFFu) - 1;
        float num = __shfl_sync(0xFFFFFFFFu, rhs,  src, 16);
        float den = __shfl_sync(0xFFFFFFFFu, A[c], src, 16);
        float xc  = __fdividef(num, den);
        if (r == c) xk = xc;
        if (mystep < c) rhs = fmaf(-A[c], xc, rhs);
    }
    out[(size_t)p * 16 + r] = m0 * sdet * xk;
}

extern "C" void kernel_launch(void* const* d_in, const int* in_sizes, int n_in,
                              void* d_out, int out_size) {
    const float* eq  = (const float*)d_in[0];
    const float* rei = (const float*)d_in[1];
    const float* Wg  = (const float*)d_in[2];
    const float* bg  = (const float*)d_in[3];
    const float* edg = (const float*)d_in[4];
    const float* eig = (const float*)d_in[5];
    float* out = (float*)d_out;
    const int smem = (int)sizeof(Smem1);
    cudaFuncSetAttribute(k1_buildM, cudaFuncAttributeMaxDynamicSharedMemorySize, smem);
    k1_buildM<<<NBLK, 256, smem>>>(eq, rei, Wg, bg, edg, eig);
    k2_solve<<<512, 256>>>(out);
}